// round 16
// baseline (speedup 1.0000x reference)
#include <cuda_runtime.h>

// Problem constants
#define HW    4096      // 64*64
#define CH    18
#define NPOS  65536     // 16 * 4096
#define NBLK  512

// Output layout (concatenated reference outputs, fp32)
#define OUT_ZQ     0
#define OUT_LOSS   1179648
#define OUT_CBENT  1179649
#define OUT_IDX    1179650
#define OUT_GIDX   1245186
#define OUT_AVGP   1376258

// Scratch (no cudaMalloc allowed). Zero-initialized at module load; every
// execution resets it to zero in the last-block epilogue, so each graph
// replay starts from a clean state (deterministic).
__device__ float    g_avg[1024];
__device__ float    g_ent;
__device__ float    g_commit;
__device__ unsigned g_ticket;

// Packed f32x2 ops (Blackwell FMA pipe; only reachable via PTX)
#define MUL2(o, a, b)    asm("mul.rn.f32x2 %0, %1, %2;" : "=l"(o) : "l"(a), "l"(b))
#define FMA2(o, a, b, c) asm("fma.rn.f32x2 %0, %1, %2, %3;" : "=l"(o) : "l"(a), "l"(b), "l"(c))
typedef unsigned long long u64;

// 512 blocks x 128 threads (4 warps). Each warp owns 32 consecutive positions.
//
// Identity: the softmax over the 512 sign codes factorizes into independent
// per-channel Bernoullis with p(s_c=+1) = sigmoid(4*z_c). Phase A additionally
// pre-multiplies CHANNEL PAIRS (all 4 sign combos) so phase B's product tree
// is only 3 levels deep:
//   base = C45[l] * C67[l] * C8[l]   (lane-selected)       3 LDS + 2 MUL2
//   r[m] = base * C23[m]             (k low bits)          4 LDS + 4 MUL2
//   acc[h*4+m] += r[m] * C01[h]      (k high bits, fused)  4 LDS + 16 FMA2
// avg_prob partials combine across the block's 4 warps in shared memory (one
// global atomic per bin per block); the LAST block (sync/fence/sync + ticket)
// finalizes loss/cb_entropy/avg_prob and resets the scratch — single kernel.
// Finalize-path scratch accesses bypass L1 (__ldcg/__stcg): atomics resolve
// at L2, so L2-coherent accesses make the replay loop airtight.
__global__ __launch_bounds__(128, 4)
void bsq_main(const float* __restrict__ z, float* __restrict__ out) {
    // Per-warp staging: 36 rows x 34 floats. Row pitch 136B = 17*8 keeps all
    // 8B loads aligned and spreads rows across bank pairs. Per group g
    // (row base g*18): rows 0-3 C01 combos, 4-7 C23, 8-11 C45, 12-15 C67,
    // 16-17 C8 (pr-, pr+). Combo row t = sigA_bit*2 + sigB_bit, bit=1 -> +1.
    // Floats [0..1023] of each warp row are reused post-compute as the
    // block-combine flush buffer.
    __shared__ float S[4][36 * 34];
    __shared__ float Fs[4][2];                   // per-warp (ent, commit)
    __shared__ float red4[4];
    __shared__ unsigned s_last;
#define SROW(w, r) (&S[w][(r) * 34])

    const int tid  = threadIdx.x;
    const int warp = tid >> 5;
    const int lane = tid & 31;

    const int tile = blockIdx.x * 4 + warp;      // 0..2047
    const int b    = tile >> 7;                  // 128 tiles per batch image
    const int hw0  = (tile & 127) << 5;

    const float* zb = z   + (size_t)b * CH * HW + hw0 + lane;
    float*       oq = out + (size_t)b * CH * HW + hw0 + lane;

    // ---------- Phase A: per-position (one per lane) ------------------------
    float commit = 0.0f, ent = 0.0f;
    unsigned idx = 0u;
    float pr1[CH], pr0[CH];                      // p(s=+1), p(s=-1) per channel
#pragma unroll
    for (int c = 0; c < CH; c++) {
        float v = zb[c * HW];
        bool pos = v > 0.0f;
        float s = pos ? 1.0f : -1.0f;
        oq[c * HW] = s;                          // zq (BCHW) == sign(z); v==0 -> -1
        float d = s - v;
        commit += d * d;
        idx = (idx << 1) | (pos ? 1u : 0u);      // channel 0 = MSB

        // Bernoulli factor: p(s=+1) = sigmoid(4v)
        float m  = 2.0f * fabsf(v);              // |a_c| = |2 z_c|
        float u  = __expf(-2.0f * m);            // exp(-4|v|) in (0,1]
        float w  = __frcp_rn(1.0f + u);          // sigmoid(4|v|)
        float uw = u * w;                        // 1 - w
        pr1[c] = pos ? w : uw;
        pr0[c] = pos ? uw : w;

        // channel entropy: H = m + log(1+u) - m*tanh(m),  tanh(m) = (1-u)*w
        ent += m + __logf(1.0f + u) - m * (1.0f - u) * w;
    }
    {
        int p = b * HW + hw0 + lane;
        out[OUT_IDX + p] = (float)idx;
        // group indices: adjacent pair -> single aligned STG.64
        float2 gi = make_float2((float)(idx >> 9), (float)(idx & 511u));
        *reinterpret_cast<float2*>(&out[OUT_GIDX + 2 * p]) = gi;
    }
    // Store pair-product combos (conflict-free: stride-1 in lane)
#pragma unroll
    for (int g = 0; g < 2; g++) {
        const int c0 = g * 9;
#pragma unroll
        for (int pp = 0; pp < 4; pp++) {         // pairs (0,1),(2,3),(4,5),(6,7)
            const int a = c0 + pp * 2;
            SROW(warp, g * 18 + pp * 4 + 0)[lane] = pr0[a] * pr0[a + 1];
            SROW(warp, g * 18 + pp * 4 + 1)[lane] = pr0[a] * pr1[a + 1];
            SROW(warp, g * 18 + pp * 4 + 2)[lane] = pr1[a] * pr0[a + 1];
            SROW(warp, g * 18 + pp * 4 + 3)[lane] = pr1[a] * pr1[a + 1];
        }
        SROW(warp, g * 18 + 16)[lane] = pr0[c0 + 8];
        SROW(warp, g * 18 + 17)[lane] = pr1[c0 + 8];
    }
    __syncwarp();

    // ---------- Phase B: 3-level product tree, f32x2 over position pairs ----
    // Code d = k*32 + lane: lane bits 4..0 -> ch 4..8, k bits 3..0 -> ch 0..3
    // (MSB-first). h = k>>2 selects C01 combo, m = k&3 selects C23 combo.
    //
    // Flush-to-shared safety: group g's partials land at floats [g*512,
    // g*512+512) of this warp's S row — only rows whose reads are complete
    // (g=0: its own staging rows; g=1: own staging + g0 leftovers).
    // __syncwarp guards write-after-read.
#pragma unroll
    for (int g = 0; g < 2; g++) {
        const int rb = g * 18;
        const float* B45 = SROW(warp, rb + 8  + ((lane >> 3) & 3));
        const float* B67 = SROW(warp, rb + 12 + ((lane >> 1) & 3));
        const float* B8  = SROW(warp, rb + 16 + (lane & 1));
        const float* M0 = SROW(warp, rb + 4); const float* M1 = SROW(warp, rb + 5);
        const float* M2 = SROW(warp, rb + 6); const float* M3 = SROW(warp, rb + 7);
        const float* H0 = SROW(warp, rb + 0); const float* H1 = SROW(warp, rb + 1);
        const float* H2 = SROW(warp, rb + 2); const float* H3 = SROW(warp, rb + 3);

        u64 acc[16];
#pragma unroll
        for (int k = 0; k < 16; k++) acc[k] = 0ull;

#pragma unroll 1
        for (int j = 0; j < 32; j += 2) {
            // 64-bit broadcast loads of position pair (j, j+1)
            u64 b45 = *(const u64*)(B45 + j);
            u64 b67 = *(const u64*)(B67 + j);
            u64 b8  = *(const u64*)(B8  + j);
            u64 t0, base;
            MUL2(t0, b45, b67);
            MUL2(base, t0, b8);

            u64 mv[4] = { *(const u64*)(M0 + j), *(const u64*)(M1 + j),
                          *(const u64*)(M2 + j), *(const u64*)(M3 + j) };
            u64 hv[4] = { *(const u64*)(H0 + j), *(const u64*)(H1 + j),
                          *(const u64*)(H2 + j), *(const u64*)(H3 + j) };

            u64 r[4];
#pragma unroll
            for (int m = 0; m < 4; m++) MUL2(r[m], base, mv[m]);

#pragma unroll
            for (int h = 0; h < 4; h++)
#pragma unroll
                for (int m = 0; m < 4; m++)
                    FMA2(acc[h * 4 + m], r[m], hv[h], acc[h * 4 + m]);
        }

        __syncwarp();                            // all reads of S done
#pragma unroll
        for (int k = 0; k < 16; k++) {           // partials -> own S row
            float2 v = *reinterpret_cast<float2*>(&acc[k]);
            S[warp][g * 512 + k * 32 + lane] = v.x + v.y;   // conflict-free STS
        }
        __syncwarp();
    }

    // ---------- Phase C: scalar reductions ----------------------------------
#pragma unroll
    for (int o = 16; o > 0; o >>= 1) {
        ent    += __shfl_xor_sync(0xffffffffu, ent, o);
        commit += __shfl_xor_sync(0xffffffffu, commit, o);
    }
    if (lane == 0) { Fs[warp][0] = ent; Fs[warp][1] = commit; }

    // ---------- Block combine + single global flush per bin -----------------
    __syncthreads();
    for (int i = tid; i < 1024; i += 128) {      // 8 bins per thread
        float s = S[0][i] + S[1][i] + S[2][i] + S[3][i];
        atomicAdd(&g_avg[i], s);                 // 1 REDG per bin per block
    }
    if (tid == 0)
        atomicAdd(&g_ent,    Fs[0][0] + Fs[1][0] + Fs[2][0] + Fs[3][0]);
    if (tid == 1)
        atomicAdd(&g_commit, Fs[0][1] + Fs[1][1] + Fs[2][1] + Fs[3][1]);

    // ---------- Last-block finalize + scratch reset -------------------------
    // Ordering: barrier so ALL threads have executed their atomics; then every
    // thread fences its writes device-wide; then barrier again so tid0's
    // ticket increment is ordered after every fence. No block ever waits on
    // another (no spin), so this is deadlock-free at any residency.
    __syncthreads();
    __threadfence();
    __syncthreads();
    if (tid == 0)
        s_last = (atomicAdd(&g_ticket, 1u) == NBLK - 1) ? 1u : 0u;
    __syncthreads();
    if (s_last) {
        float part = 0.0f;
        for (int i = tid; i < 1024; i += 128) {
            // __ldcg: L2-coherent read (atomics resolved at L2, never in L1)
            float avg = __ldcg(&g_avg[i]) * (1.0f / (float)NPOS);
            out[OUT_AVGP + i] = avg;
            part -= avg * logf(avg + 1e-8f);     // exact eps form for cb_entropy
            __stcg(&g_avg[i], 0.0f);             // reset lands in L2 for replay
        }
#pragma unroll
        for (int o = 16; o > 0; o >>= 1)
            part += __shfl_xor_sync(0xffffffffu, part, o);
        if (lane == 0) red4[warp] = part;
        __syncthreads();
        if (tid == 0) {
            float cb      = red4[0] + red4[1] + red4[2] + red4[3];
            float commitl = 0.25f * __ldcg(&g_commit) * (1.0f / (float)NPOS);
            float psent   = __ldcg(&g_ent) * (1.0f / (float)NPOS);
            out[OUT_LOSS]  = commitl + psent - cb;   // gamma0=gamma=zeta=inv_t=1
            out[OUT_CBENT] = cb;
            __stcg(&g_ent, 0.0f);
            __stcg(&g_commit, 0.0f);
            __stcg(&g_ticket, 0u);               // clean state for next replay
        }
    }
#undef SROW
}

extern "C" void kernel_launch(void* const* d_in, const int* in_sizes, int n_in,
                              void* d_out, int out_size) {
    const float* z = (const float*)d_in[0];
    float* out = (float*)d_out;
    bsq_main<<<NBLK, 128>>>(z, out);
}